// round 15
// baseline (speedup 1.0000x reference)
#include <cuda_runtime.h>

#define PNUM 16320
#define BATCH 32
#define NCLS 21
#define TOPK 500
#define CONF_THV 0.01f
#define NMS_THV 0.45f
#define OBJ_THV 0.01f
#define NT 256
// TH/(1+TH) for the transformed suppression test
#define NMS_COEF 0.310344827586206896f
#define NQ4 4080   // PNUM/4 float4 loads

// ---- device scratch (no allocations allowed) ----
__device__ float4 g_boxes[BATCH * PNUM];                 // decoded boxes (x1,y1,x2,y2)
__device__ float  g_scores[BATCH * (NCLS - 1) * PNUM];   // arm-masked scores, [B][20][P]

// ---- shared memory layout (bytes) ----
#define OFF_MISC   0        // 64 (16 u32)
#define OFF_SEL    64       // 512*8 = 4096 (u64 keys: score||~idx)
#define OFF_BOX    4160     // 512*16 = 8192 (16B aligned)
#define OFF_AREA   12352    // 2048  (holds c_i = NMS_COEF * area_i)
#define OFF_PORD   14400    // 2048
#define OFF_MAT    16448    // triangle-packed 4352 words = 17408
#define SMEM_TOTAL 33856    // 5 blocks/SM (reg-capped), single wave
// overlays inside MAT (dead until matrix phase)
#define OFF_HIST   16448    // 2048*4 = 8192
#define OFF_PART   24640    // 256*4
#define OFF_WSUM   25664    // 8*4
#define OFF_EQ     25696    // 512*8 = 4096 (u64 boundary-bin keys)

// misc: 1=ncomp 4=take 6=K 7=cnt 8=bsel 9=neq

// triangle packing: rows grouped by block rb=r>>5; row r stores words rb..15
__host__ __device__ __forceinline__ int tri_base(int rb) {
    return 512 * rb - 16 * rb * (rb - 1);
}

// 72 equal 32x32 tiles (p=column pair, rb=row block; rb <= 2p+1), 9 per warp
__device__ __constant__ unsigned char TP[72] = {
    0,0, 1,1,1,1, 2,2,2,2,2,2, 3,3,3,3,3,3,3,3,
    4,4,4,4,4,4,4,4,4,4, 5,5,5,5,5,5,5,5,5,5,5,5,
    6,6,6,6,6,6,6,6,6,6,6,6,6,6, 7,7,7,7,7,7,7,7,7,7,7,7,7,7,7,7};
__device__ __constant__ unsigned char TRB[72] = {
    0,1, 0,1,2,3, 0,1,2,3,4,5, 0,1,2,3,4,5,6,7,
    0,1,2,3,4,5,6,7,8,9, 0,1,2,3,4,5,6,7,8,9,10,11,
    0,1,2,3,4,5,6,7,8,9,10,11,12,13, 0,1,2,3,4,5,6,7,8,9,10,11,12,13,14,15};

// =====================================================================
// Kernel 1: cascaded decode + arm-masked score transpose
// =====================================================================
__global__ void prep_kernel(const float* __restrict__ arm_loc,
                            const float* __restrict__ arm_conf,
                            const float* __restrict__ odm_loc,
                            const float* __restrict__ odm_conf,
                            const float* __restrict__ priors) {
    int idx = blockIdx.x * blockDim.x + threadIdx.x;
    if (idx >= BATCH * PNUM) return;
    int b = idx / PNUM;
    int p = idx % PNUM;

    float pcx = priors[p * 4 + 0];
    float pcy = priors[p * 4 + 1];
    float pw  = priors[p * 4 + 2];
    float ph  = priors[p * 4 + 3];

    const float* al = arm_loc + (size_t)idx * 4;
    const float* ol = odm_loc + (size_t)idx * 4;

    float cx = pcx + al[0] * 0.1f * pw;
    float cy = pcy + al[1] * 0.1f * ph;
    float w  = pw * expf(al[2] * 0.2f);
    float h  = ph * expf(al[3] * 0.2f);
    float mnx = cx - w * 0.5f;
    float mny = cy - h * 0.5f;
    float mxx = mnx + w;
    float mxy = mny + h;
    float dcx = (mxx + mnx) * 0.5f;
    float dcy = (mxy + mny) * 0.5f;
    float dw  = mxx - mnx;
    float dh  = mxy - mny;

    float cx2 = dcx + ol[0] * 0.1f * dw;
    float cy2 = dcy + ol[1] * 0.1f * dh;
    float w2  = dw * expf(ol[2] * 0.2f);
    float h2  = dh * expf(ol[3] * 0.2f);
    float x1 = cx2 - w2 * 0.5f;
    float y1 = cy2 - h2 * 0.5f;
    float x2 = x1 + w2;
    float y2 = y1 + h2;
    g_boxes[idx] = make_float4(x1, y1, x2, y2);

    bool armpass = arm_conf[(size_t)idx * 2 + 1] > OBJ_THV;
    const float* oc = odm_conf + (size_t)idx * NCLS;
#pragma unroll
    for (int c = 1; c < NCLS; ++c) {
        float v = armpass ? oc[c] : 0.0f;
        g_scores[((size_t)(b * (NCLS - 1) + (c - 1))) * PNUM + p] = v;
    }
}

// =====================================================================
// Kernel 2: one block per (image, fg-class), 256 threads. Linear-bin
// 2-scan exact top-K select (u64 keys), hybrid shfl/smem u64 bitonic
// sort, adjacent-pair LUT-balanced suppression matrix, serial NMS walk.
// Output pre-zeroed by memset; only live rows written.
// =====================================================================
__global__ void __launch_bounds__(NT, 5) task_kernel(float* __restrict__ out) {
    extern __shared__ __align__(16) char smraw[];
    unsigned*           misc = (unsigned*)(smraw + OFF_MISC);
    unsigned long long* sel  = (unsigned long long*)(smraw + OFF_SEL);
    float4*             bx4  = (float4*)(smraw + OFF_BOX);
    float*              s_c  = (float*)(smraw + OFF_AREA);
    int*                pord = (int*)(smraw + OFF_PORD);
    unsigned*           mat  = (unsigned*)(smraw + OFF_MAT);
    unsigned*           hist = (unsigned*)(smraw + OFF_HIST);
    unsigned*           part = (unsigned*)(smraw + OFF_PART);
    unsigned*           wsum = (unsigned*)(smraw + OFF_WSUM);
    unsigned long long* eqk  = (unsigned long long*)(smraw + OFF_EQ);

    const int tid = threadIdx.x;
    const int b   = blockIdx.x / (NCLS - 1);
    const int cl  = blockIdx.x % (NCLS - 1) + 1;     // fg classes only
    float* outp = out + (size_t)(b * NCLS + cl) * (TOPK * 5);

    const float* __restrict__ sp =
        g_scores + (size_t)(b * (NCLS - 1) + (cl - 1)) * PNUM;
    const float4* __restrict__ sp4 = (const float4*)sp;

    // ======== SCAN 1: 2048 linear-bin histogram (bin = s*2047, monotone) ====
    for (int h = tid; h < 2048; h += NT) hist[h] = 0u;
    if (tid < 16) misc[tid] = 0u;
    __syncthreads();

#pragma unroll 1
    for (int it = 0; it < 16; ++it) {          // uniform trip count
        int j4 = it * NT + tid;
        float4 sv = make_float4(0.f, 0.f, 0.f, 0.f);
        bool inb = j4 < NQ4;
        if (inb) sv = sp4[j4];
#pragma unroll
        for (int e = 0; e < 4; ++e) {
            float s = (e == 0) ? sv.x : (e == 1) ? sv.y : (e == 2) ? sv.z : sv.w;
            int bin = (inb && s > CONF_THV) ? min((int)(s * 2047.0f), 2047) : -1;
            unsigned grp = __match_any_sync(0xFFFFFFFFu, bin);
            if (((unsigned)tid & 31u) == (unsigned)(__ffs(grp) - 1) && bin >= 0)
                atomicAdd(&hist[bin], (unsigned)__popc(grp));
        }
    }
    __syncthreads();
    {   // reduce 2048 bins: 8/thread -> part[256] -> wsum[8]
        unsigned v = 0;
#pragma unroll
        for (int q = 0; q < 8; ++q) v += hist[tid * 8 + q];
        part[tid] = v;
#pragma unroll
        for (int o = 16; o; o >>= 1) v += __shfl_down_sync(0xFFFFFFFFu, v, o);
        if ((tid & 31) == 0) wsum[tid >> 5] = v;
    }
    __syncthreads();
    if (tid == 0) {
        unsigned total = 0;
        for (int l = 0; l < 8; ++l) total += wsum[l];
        unsigned K = total < TOPK ? total : TOPK;
        misc[6] = K;
        if (K > 0) {
            unsigned rem = K, cum = 0;
            int l = 7;
            for (;; --l) { unsigned v = wsum[l]; if (cum + v >= rem) break; cum += v; }
            int p = l * 32 + 31;
            for (;; --p) { unsigned v = part[p]; if (cum + v >= rem) break; cum += v; }
            int bb = p * 8 + 7;
            for (;; --bb) { unsigned v = hist[bb]; if (cum + v >= rem) break; cum += v; }
            misc[8] = (unsigned)bb;
            misc[4] = rem - cum;       // take from boundary bin
        }
    }
    __syncthreads();

    const int K = (int)misc[6];
    if (K == 0) return;                // output already zero (memset)

    // ======== SCAN 2: merged compact ========
    // bin > bsel  -> surely selected: write u64 key to sel (ballot-compacted)
    // bin == bsel -> boundary candidate: append key to eq list (~8 expected)
    const int bsel = (int)misc[8];
#pragma unroll 1
    for (int it = 0; it < 16; ++it) {                  // uniform trips (ballot)
        int j4 = it * NT + tid;
        float4 sv = make_float4(0.f, 0.f, 0.f, 0.f);
        bool inb = j4 < NQ4;
        if (inb) sv = sp4[j4];
#pragma unroll
        for (int e = 0; e < 4; ++e) {
            float s = (e == 0) ? sv.x : (e == 1) ? sv.y : (e == 2) ? sv.z : sv.w;
            int bin = (inb && s > CONF_THV) ? (int)(s * 2047.0f) : -1;
            bool selb = bin > bsel;
            unsigned long long key =
                ((unsigned long long)__float_as_uint(s) << 32) |
                (unsigned long long)(0xFFFFFFFFu - (unsigned)(j4 * 4 + e));
            unsigned m = __ballot_sync(0xFFFFFFFFu, selb);
            unsigned base = 0;
            if ((tid & 31) == 0 && m) base = atomicAdd(&misc[1], (unsigned)__popc(m));
            base = __shfl_sync(0xFFFFFFFFu, base, 0);
            if (selb)
                sel[base + __popc(m & ((1u << (tid & 31)) - 1u))] = key;
            if (bin == bsel) {
                unsigned p = atomicAdd(&misc[9], 1u);
                if (p < 512) eqk[p] = key;
            }
        }
    }
    __syncthreads();
    if (tid == 0) {    // pick the 'take' largest keys from the boundary bin
        int neq = (int)misc[9]; if (neq > 512) neq = 512;
        int tk = (int)misc[4]; if (tk > neq) tk = neq;
        int base = (int)misc[1];
        for (int t = 0; t < tk; ++t) {
            unsigned long long best = 0ull; int bi = 0;
            for (int q = 0; q < neq; ++q)
                if (eqk[q] > best) { best = eqk[q]; bi = q; }
            eqk[bi] = 0ull;
            sel[base + t] = best;
        }
        misc[1] = (unsigned)(base + tk);
    }
    __syncthreads();
    for (int i = tid; i < 512; i += NT)
        if (i >= K) sel[i] = (unsigned long long)(0xBFFFFFFFu - i);  // hi32=0: sorts last
    __syncthreads();

    // ======== hybrid bitonic sort: 512 u64 keys, descending ========
    {
        unsigned long long e0 = sel[tid], e1 = sel[tid + 256];
#pragma unroll
        for (unsigned k = 2; k <= 32; k <<= 1) {
#pragma unroll
            for (unsigned jj = k >> 1; jj > 0; jj >>= 1) {
                unsigned long long p0 = __shfl_xor_sync(0xFFFFFFFFu, e0, jj);
                unsigned long long p1 = __shfl_xor_sync(0xFFFFFFFFu, e1, jj);
                bool lo = (((unsigned)tid & jj) == 0);
                bool up0 = ((((unsigned)tid) & k) == 0) == lo;
                bool up1 = ((((unsigned)tid + 256u) & k) == 0) == lo;
                e0 = up0 ? (e0 > p0 ? e0 : p0) : (e0 < p0 ? e0 : p0);
                e1 = up1 ? (e1 > p1 ? e1 : p1) : (e1 < p1 ? e1 : p1);
            }
        }
        sel[tid] = e0; sel[tid + 256] = e1;
        __syncthreads();
#pragma unroll 1
        for (unsigned k = 64; k <= 512; k <<= 1) {
            for (unsigned jj = k >> 1; jj >= 32; jj >>= 1) {
#pragma unroll
                for (int half = 0; half < 512; half += NT) {
                    unsigned i = (unsigned)(half + tid);
                    unsigned ixj = i ^ jj;
                    if (ixj > i) {
                        unsigned long long a = sel[i], x = sel[ixj];
                        bool g = x > a;
                        bool asc = ((i & k) == 0);
                        if (asc ? g : !g) { sel[i] = x; sel[ixj] = a; }
                    }
                }
                __syncthreads();
            }
            e0 = sel[tid]; e1 = sel[tid + 256];
#pragma unroll
            for (unsigned jj = 16; jj > 0; jj >>= 1) {
                unsigned long long p0 = __shfl_xor_sync(0xFFFFFFFFu, e0, jj);
                unsigned long long p1 = __shfl_xor_sync(0xFFFFFFFFu, e1, jj);
                bool lo = (((unsigned)tid & jj) == 0);
                bool up0 = ((((unsigned)tid) & k) == 0) == lo;
                bool up1 = ((((unsigned)tid + 256u) & k) == 0) == lo;
                e0 = up0 ? (e0 > p0 ? e0 : p0) : (e0 < p0 ? e0 : p0);
                e1 = up1 ? (e1 > p1 ? e1 : p1) : (e1 < p1 ? e1 : p1);
            }
            sel[tid] = e0; sel[tid + 256] = e1;
            __syncthreads();
        }
    }

    // ======== gather boxes + precompute c_i = NMS_COEF * area_i ========
    for (int i = tid; i < 512; i += NT) {
        float4 bb = make_float4(0.f, 0.f, 0.f, 0.f);
        float a = 0.f;
        if (i < K) {
            unsigned idx = 0xFFFFFFFFu - (unsigned)sel[i];
            bb = g_boxes[(size_t)b * PNUM + idx];
            a = (bb.z - bb.x) * (bb.w - bb.y);
        }
        bx4[i] = bb;
        s_c[i] = NMS_COEF * a;
    }
    __syncthreads();

    // ======== suppression matrix over 72 balanced adjacent-pair tiles ========
    // sup(i,j) == fmaf(iw, ih, -(c_i+c_j)) > 0 ; iw clamped, ih clamp dropped
    {
        const int w    = tid >> 5;
        const int lane = tid & 31;
#pragma unroll 1
        for (int tt = 0; tt < 9; ++tt) {
            const int t  = w + tt * 8;
            const int p  = TP[t];
            const int rb = TRB[t];
            const int W1 = 2 * p;
            const int W2 = W1 + 1;
            const int j1 = (W1 << 5) + lane;
            const int j2 = (W2 << 5) + lane;
            const float4 b1 = bx4[j1];
            const float  c1 = s_c[j1];
            const float4 b2 = bx4[j2];
            const float  c2 = s_c[j2];
            const bool do1 = (rb <= W1);               // warp-uniform
            const int nw = 16 - rb;
            unsigned* dst1 = mat + tri_base(rb) + (W1 - rb);
#pragma unroll 4
            for (int rr = 0; rr < 32; ++rr) {
                const int r = (rb << 5) + rr;
                const float4 bi = bx4[r];               // broadcast LDS.128
                const float  ci = s_c[r];
                float xx1 = fmaxf(bi.x, b2.x);
                float yy1 = fmaxf(bi.y, b2.y);
                float xx2 = fminf(bi.z, b2.z);
                float yy2 = fminf(bi.w, b2.w);
                float iw = fmaxf(xx2 - xx1, 0.0f);
                float ih = yy2 - yy1;                   // unclamped: safe
                bool sup2 = fmaf(iw, ih, -(ci + c2)) > 0.0f;
                unsigned bits2 = __ballot_sync(0xFFFFFFFFu, sup2);
                float ax1 = fmaxf(bi.x, b1.x);
                float ay1 = fmaxf(bi.y, b1.y);
                float ax2 = fminf(bi.z, b1.z);
                float ay2 = fminf(bi.w, b1.w);
                float aw = fmaxf(ax2 - ax1, 0.0f);
                float ah = ay2 - ay1;                   // unclamped: safe
                bool sup1 = fmaf(aw, ah, -(ci + c1)) > 0.0f;
                unsigned bits1 = __ballot_sync(0xFFFFFFFFu, sup1);
                if (lane == 0) {
                    dst1[rr * nw + 1] = bits2;
                    if (do1) dst1[rr * nw] = bits1;
                }
            }
        }
    }
    __syncthreads();

    // ======== serial NMS walk (thread 0, alive in regs) ========
    if (tid == 0) {
        unsigned alive[16];
#pragma unroll
        for (int ww = 0; ww < 16; ++ww) {
            int n = K - ww * 32;
            alive[ww] = (n >= 32) ? 0xFFFFFFFFu : (n > 0 ? ((1u << n) - 1u) : 0u);
        }
        int cnt = 0;
#pragma unroll
        for (int W = 0; W < 16; ++W) {
            const int nw = 16 - W;
            const unsigned* blk = mat + tri_base(W);
            unsigned cur = alive[W];
            while (cur) {
                int bit = __ffs(cur) - 1;
                pord[cnt++] = (W << 5) + bit;
                const unsigned* mrow = blk + bit * nw;
                cur &= ~mrow[0];                 // self bit clears (iou=1 > TH)
                cur &= ~(1u << bit);
#pragma unroll
                for (int ww = W + 1; ww < 16; ++ww)
                    alive[ww] &= ~mrow[ww - W];
            }
        }
        misc[7] = (unsigned)cnt;
    }
    __syncthreads();

    // ======== writeout (live rows only; rest zero via memset) ========
    const int cnt = (int)misc[7];
    for (int t = tid; t < cnt; t += NT) {
        int p = pord[t];
        float4 bb = bx4[p];
        outp[t * 5 + 0] = __uint_as_float((unsigned)(sel[p] >> 32));
        outp[t * 5 + 1] = bb.x;
        outp[t * 5 + 2] = bb.y;
        outp[t * 5 + 3] = bb.z;
        outp[t * 5 + 4] = bb.w;
    }
}

extern "C" void kernel_launch(void* const* d_in, const int* in_sizes, int n_in,
                              void* d_out, int out_size) {
    const float* arm_loc  = (const float*)d_in[0];
    const float* arm_conf = (const float*)d_in[1];
    const float* odm_loc  = (const float*)d_in[2];
    const float* odm_conf = (const float*)d_in[3];
    const float* priors   = (const float*)d_in[4];
    float* out = (float*)d_out;

    cudaFuncSetAttribute(task_kernel, cudaFuncAttributeMaxDynamicSharedMemorySize,
                         SMEM_TOTAL);

    cudaMemsetAsync(out, 0, (size_t)out_size * sizeof(float));
    int total = BATCH * PNUM;
    prep_kernel<<<(total + 255) / 256, 256>>>(arm_loc, arm_conf, odm_loc, odm_conf,
                                              priors);
    task_kernel<<<BATCH * (NCLS - 1), NT, SMEM_TOTAL>>>(out);
}

// round 16
// speedup vs baseline: 1.4407x; 1.4407x over previous
#include <cuda_runtime.h>

#define PNUM 16320
#define BATCH 32
#define NCLS 21
#define TOPK 500
#define CONF_THV 0.01f
#define NMS_THV 0.45f
#define OBJ_THV 0.01f
#define NT 256
// TH/(1+TH) for the transformed suppression test
#define NMS_COEF 0.310344827586206896f
#define NQ4 4080   // PNUM/4 float4 loads

// ---- device scratch (no allocations allowed) ----
__device__ float4 g_boxes[BATCH * PNUM];                 // decoded boxes (x1,y1,x2,y2)
__device__ float  g_scores[BATCH * (NCLS - 1) * PNUM];   // arm-masked scores, [B][20][P]

// ---- shared memory layout (bytes) ----
#define OFF_MISC   0        // 64 (16 u32)
#define OFF_SEL    64       // 512*8 = 4096 (u64 keys: score||~idx)
#define OFF_BOX    4160     // 512*16 = 8192 (16B aligned)
#define OFF_AREA   12352    // 2048  (holds c_i = NMS_COEF * area_i)
#define OFF_PORD   14400    // 2048
#define OFF_MAT    16448    // triangle-packed 4352 words = 17408
#define SMEM_TOTAL 33856    // 5 blocks/SM (reg-capped), single wave
// overlays inside MAT (dead until matrix phase)
#define OFF_HIST   16448    // 2048*4 = 8192
#define OFF_PART   24640    // 256*4
#define OFF_WSUM   25664    // 8*4
#define OFF_EQ     25696    // 512*8 = 4096 (u64 boundary-bin keys)

// misc: 1=ncomp 4=take 6=K 7=cnt 8=bsel 9=neq

// triangle packing: rows grouped by block rb=r>>5; row r stores words rb..15
__host__ __device__ __forceinline__ int tri_base(int rb) {
    return 512 * rb - 16 * rb * (rb - 1);
}

// 72 equal 32x32 tiles (p=column pair, rb=row block; rb <= 2p+1), 9 per warp
__device__ __constant__ unsigned char TP[72] = {
    0,0, 1,1,1,1, 2,2,2,2,2,2, 3,3,3,3,3,3,3,3,
    4,4,4,4,4,4,4,4,4,4, 5,5,5,5,5,5,5,5,5,5,5,5,
    6,6,6,6,6,6,6,6,6,6,6,6,6,6, 7,7,7,7,7,7,7,7,7,7,7,7,7,7,7,7};
__device__ __constant__ unsigned char TRB[72] = {
    0,1, 0,1,2,3, 0,1,2,3,4,5, 0,1,2,3,4,5,6,7,
    0,1,2,3,4,5,6,7,8,9, 0,1,2,3,4,5,6,7,8,9,10,11,
    0,1,2,3,4,5,6,7,8,9,10,11,12,13, 0,1,2,3,4,5,6,7,8,9,10,11,12,13,14,15};

// =====================================================================
// Kernel 1: cascaded decode + arm-masked score transpose
// =====================================================================
__global__ void prep_kernel(const float* __restrict__ arm_loc,
                            const float* __restrict__ arm_conf,
                            const float* __restrict__ odm_loc,
                            const float* __restrict__ odm_conf,
                            const float* __restrict__ priors) {
    int idx = blockIdx.x * blockDim.x + threadIdx.x;
    if (idx >= BATCH * PNUM) return;
    int b = idx / PNUM;
    int p = idx % PNUM;

    float pcx = priors[p * 4 + 0];
    float pcy = priors[p * 4 + 1];
    float pw  = priors[p * 4 + 2];
    float ph  = priors[p * 4 + 3];

    const float* al = arm_loc + (size_t)idx * 4;
    const float* ol = odm_loc + (size_t)idx * 4;

    float cx = pcx + al[0] * 0.1f * pw;
    float cy = pcy + al[1] * 0.1f * ph;
    float w  = pw * expf(al[2] * 0.2f);
    float h  = ph * expf(al[3] * 0.2f);
    float mnx = cx - w * 0.5f;
    float mny = cy - h * 0.5f;
    float mxx = mnx + w;
    float mxy = mny + h;
    float dcx = (mxx + mnx) * 0.5f;
    float dcy = (mxy + mny) * 0.5f;
    float dw  = mxx - mnx;
    float dh  = mxy - mny;

    float cx2 = dcx + ol[0] * 0.1f * dw;
    float cy2 = dcy + ol[1] * 0.1f * dh;
    float w2  = dw * expf(ol[2] * 0.2f);
    float h2  = dh * expf(ol[3] * 0.2f);
    float x1 = cx2 - w2 * 0.5f;
    float y1 = cy2 - h2 * 0.5f;
    float x2 = x1 + w2;
    float y2 = y1 + h2;
    g_boxes[idx] = make_float4(x1, y1, x2, y2);

    bool armpass = arm_conf[(size_t)idx * 2 + 1] > OBJ_THV;
    const float* oc = odm_conf + (size_t)idx * NCLS;
#pragma unroll
    for (int c = 1; c < NCLS; ++c) {
        float v = armpass ? oc[c] : 0.0f;
        g_scores[((size_t)(b * (NCLS - 1) + (c - 1))) * PNUM + p] = v;
    }
}

// =====================================================================
// Kernel 2: per (image,class), 256 threads. Linear-bin 2-scan exact
// top-K select (u64 keys), hybrid shfl/smem u64 bitonic sort,
// adjacent-pair LUT-balanced suppression matrix, serial NMS walk
// OVERLAPPED with output zero-fill by warps 1..7.
// =====================================================================
__global__ void __launch_bounds__(NT, 5) task_kernel(float* __restrict__ out) {
    extern __shared__ __align__(16) char smraw[];
    unsigned*           misc = (unsigned*)(smraw + OFF_MISC);
    unsigned long long* sel  = (unsigned long long*)(smraw + OFF_SEL);
    float4*             bx4  = (float4*)(smraw + OFF_BOX);
    float*              s_c  = (float*)(smraw + OFF_AREA);
    int*                pord = (int*)(smraw + OFF_PORD);
    unsigned*           mat  = (unsigned*)(smraw + OFF_MAT);
    unsigned*           hist = (unsigned*)(smraw + OFF_HIST);
    unsigned*           part = (unsigned*)(smraw + OFF_PART);
    unsigned*           wsum = (unsigned*)(smraw + OFF_WSUM);
    unsigned long long* eqk  = (unsigned long long*)(smraw + OFF_EQ);

    const int tid = threadIdx.x;
    const int b   = blockIdx.x / NCLS;
    const int cl  = blockIdx.x % NCLS;
    float* outp = out + (size_t)(b * NCLS + cl) * (TOPK * 5);

    if (cl == 0) {  // background class: all zeros
        for (int e = tid; e < TOPK * 5; e += NT) outp[e] = 0.0f;
        return;
    }

    const float* __restrict__ sp =
        g_scores + (size_t)(b * (NCLS - 1) + (cl - 1)) * PNUM;
    const float4* __restrict__ sp4 = (const float4*)sp;

    // ======== SCAN 1: 2048 linear-bin histogram (bin = s*2047, monotone) ====
    // Bins are uniformly spread -> plain atomicAdd (no match_any overhead).
    for (int h = tid; h < 2048; h += NT) hist[h] = 0u;
    if (tid < 16) misc[tid] = 0u;
    __syncthreads();

    for (int j4 = tid; j4 < NQ4; j4 += NT) {   // no collectives: divergence OK
        float4 sv = sp4[j4];
#pragma unroll
        for (int e = 0; e < 4; ++e) {
            float s = (e == 0) ? sv.x : (e == 1) ? sv.y : (e == 2) ? sv.z : sv.w;
            if (s > CONF_THV)
                atomicAdd(&hist[min((int)(s * 2047.0f), 2047)], 1u);
        }
    }
    __syncthreads();
    {   // reduce 2048 bins: 8/thread -> part[256] -> wsum[8]
        unsigned v = 0;
#pragma unroll
        for (int q = 0; q < 8; ++q) v += hist[tid * 8 + q];
        part[tid] = v;
#pragma unroll
        for (int o = 16; o; o >>= 1) v += __shfl_down_sync(0xFFFFFFFFu, v, o);
        if ((tid & 31) == 0) wsum[tid >> 5] = v;
    }
    __syncthreads();
    if (tid == 0) {
        unsigned total = 0;
        for (int l = 0; l < 8; ++l) total += wsum[l];
        unsigned K = total < TOPK ? total : TOPK;
        misc[6] = K;
        if (K > 0) {
            unsigned rem = K, cum = 0;
            int l = 7;
            for (;; --l) { unsigned v = wsum[l]; if (cum + v >= rem) break; cum += v; }
            int p = l * 32 + 31;
            for (;; --p) { unsigned v = part[p]; if (cum + v >= rem) break; cum += v; }
            int bb = p * 8 + 7;
            for (;; --bb) { unsigned v = hist[bb]; if (cum + v >= rem) break; cum += v; }
            misc[8] = (unsigned)bb;
            misc[4] = rem - cum;       // take from boundary bin
        }
    }
    __syncthreads();

    const int K = (int)misc[6];
    if (K == 0) {
        for (int e = tid; e < TOPK * 5; e += NT) outp[e] = 0.0f;
        return;
    }

    // ======== SCAN 2: merged compact ========
    // bin > bsel  -> surely selected: ballot-compacted u64 key into sel
    // bin == bsel -> boundary candidate: append key to eq list (~8 expected)
    const int bsel = (int)misc[8];
#pragma unroll 1
    for (int it = 0; it < 16; ++it) {                  // uniform trips (ballot)
        int j4 = it * NT + tid;
        float4 sv = make_float4(0.f, 0.f, 0.f, 0.f);
        bool inb = j4 < NQ4;
        if (inb) sv = sp4[j4];
#pragma unroll
        for (int e = 0; e < 4; ++e) {
            float s = (e == 0) ? sv.x : (e == 1) ? sv.y : (e == 2) ? sv.z : sv.w;
            int bin = (inb && s > CONF_THV) ? min((int)(s * 2047.0f), 2047) : -1;
            bool selb = bin > bsel;
            unsigned long long key =
                ((unsigned long long)__float_as_uint(s) << 32) |
                (unsigned long long)(0xFFFFFFFFu - (unsigned)(j4 * 4 + e));
            unsigned m = __ballot_sync(0xFFFFFFFFu, selb);
            unsigned base = 0;
            if ((tid & 31) == 0 && m) base = atomicAdd(&misc[1], (unsigned)__popc(m));
            base = __shfl_sync(0xFFFFFFFFu, base, 0);
            if (selb)
                sel[base + __popc(m & ((1u << (tid & 31)) - 1u))] = key;
            if (bin == bsel) {
                unsigned p = atomicAdd(&misc[9], 1u);
                if (p < 512) eqk[p] = key;
            }
        }
    }
    __syncthreads();
    if (tid == 0) {    // pick the 'take' largest keys from the boundary bin
        int neq = (int)misc[9]; if (neq > 512) neq = 512;
        int tk = (int)misc[4]; if (tk > neq) tk = neq;
        int base = (int)misc[1];
        for (int t = 0; t < tk; ++t) {
            unsigned long long best = 0ull; int bi = 0;
            for (int q = 0; q < neq; ++q)
                if (eqk[q] > best) { best = eqk[q]; bi = q; }
            eqk[bi] = 0ull;
            sel[base + t] = best;
        }
        misc[1] = (unsigned)(base + tk);
    }
    __syncthreads();
    for (int i = tid; i < 512; i += NT)
        if (i >= K) sel[i] = (unsigned long long)(0xBFFFFFFFu - i);  // hi32=0: sorts last
    __syncthreads();

    // ======== hybrid bitonic sort: 512 u64 keys, descending ========
    {
        unsigned long long e0 = sel[tid], e1 = sel[tid + 256];
#pragma unroll
        for (unsigned k = 2; k <= 32; k <<= 1) {
#pragma unroll
            for (unsigned jj = k >> 1; jj > 0; jj >>= 1) {
                unsigned long long p0 = __shfl_xor_sync(0xFFFFFFFFu, e0, jj);
                unsigned long long p1 = __shfl_xor_sync(0xFFFFFFFFu, e1, jj);
                bool lo = (((unsigned)tid & jj) == 0);
                bool up0 = ((((unsigned)tid) & k) == 0) == lo;
                bool up1 = ((((unsigned)tid + 256u) & k) == 0) == lo;
                e0 = up0 ? (e0 > p0 ? e0 : p0) : (e0 < p0 ? e0 : p0);
                e1 = up1 ? (e1 > p1 ? e1 : p1) : (e1 < p1 ? e1 : p1);
            }
        }
        sel[tid] = e0; sel[tid + 256] = e1;
        __syncthreads();
#pragma unroll 1
        for (unsigned k = 64; k <= 512; k <<= 1) {
            for (unsigned jj = k >> 1; jj >= 32; jj >>= 1) {
#pragma unroll
                for (int half = 0; half < 512; half += NT) {
                    unsigned i = (unsigned)(half + tid);
                    unsigned ixj = i ^ jj;
                    if (ixj > i) {
                        unsigned long long a = sel[i], x = sel[ixj];
                        bool g = x > a;
                        bool asc = ((i & k) == 0);
                        if (asc ? g : !g) { sel[i] = x; sel[ixj] = a; }
                    }
                }
                __syncthreads();
            }
            e0 = sel[tid]; e1 = sel[tid + 256];
#pragma unroll
            for (unsigned jj = 16; jj > 0; jj >>= 1) {
                unsigned long long p0 = __shfl_xor_sync(0xFFFFFFFFu, e0, jj);
                unsigned long long p1 = __shfl_xor_sync(0xFFFFFFFFu, e1, jj);
                bool lo = (((unsigned)tid & jj) == 0);
                bool up0 = ((((unsigned)tid) & k) == 0) == lo;
                bool up1 = ((((unsigned)tid + 256u) & k) == 0) == lo;
                e0 = up0 ? (e0 > p0 ? e0 : p0) : (e0 < p0 ? e0 : p0);
                e1 = up1 ? (e1 > p1 ? e1 : p1) : (e1 < p1 ? e1 : p1);
            }
            sel[tid] = e0; sel[tid + 256] = e1;
            __syncthreads();
        }
    }

    // ======== gather boxes + precompute c_i = NMS_COEF * area_i ========
    for (int i = tid; i < 512; i += NT) {
        float4 bb = make_float4(0.f, 0.f, 0.f, 0.f);
        float a = 0.f;
        if (i < K) {
            unsigned idx = 0xFFFFFFFFu - (unsigned)sel[i];
            bb = g_boxes[(size_t)b * PNUM + idx];
            a = (bb.z - bb.x) * (bb.w - bb.y);
        }
        bx4[i] = bb;
        s_c[i] = NMS_COEF * a;
    }
    __syncthreads();

    // ======== suppression matrix over 72 balanced adjacent-pair tiles ========
    // sup(i,j) == fmaf(iw, ih, -(c_i+c_j)) > 0 ; iw clamped, ih clamp dropped
    {
        const int w    = tid >> 5;
        const int lane = tid & 31;
#pragma unroll 1
        for (int tt = 0; tt < 9; ++tt) {
            const int t  = w + tt * 8;
            const int p  = TP[t];
            const int rb = TRB[t];
            const int W1 = 2 * p;
            const int W2 = W1 + 1;
            const int j1 = (W1 << 5) + lane;
            const int j2 = (W2 << 5) + lane;
            const float4 b1 = bx4[j1];
            const float  c1 = s_c[j1];
            const float4 b2 = bx4[j2];
            const float  c2 = s_c[j2];
            const bool do1 = (rb <= W1);               // warp-uniform
            const int nw = 16 - rb;
            unsigned* dst1 = mat + tri_base(rb) + (W1 - rb);
#pragma unroll 4
            for (int rr = 0; rr < 32; ++rr) {
                const int r = (rb << 5) + rr;
                const float4 bi = bx4[r];               // broadcast LDS.128
                const float  ci = s_c[r];
                float xx1 = fmaxf(bi.x, b2.x);
                float yy1 = fmaxf(bi.y, b2.y);
                float xx2 = fminf(bi.z, b2.z);
                float yy2 = fminf(bi.w, b2.w);
                float iw = fmaxf(xx2 - xx1, 0.0f);
                float ih = yy2 - yy1;                   // unclamped: safe
                bool sup2 = fmaf(iw, ih, -(ci + c2)) > 0.0f;
                unsigned bits2 = __ballot_sync(0xFFFFFFFFu, sup2);
                float ax1 = fmaxf(bi.x, b1.x);
                float ay1 = fmaxf(bi.y, b1.y);
                float ax2 = fminf(bi.z, b1.z);
                float ay2 = fminf(bi.w, b1.w);
                float aw = fmaxf(ax2 - ax1, 0.0f);
                float ah = ay2 - ay1;                   // unclamped: safe
                bool sup1 = fmaf(aw, ah, -(ci + c1)) > 0.0f;
                unsigned bits1 = __ballot_sync(0xFFFFFFFFu, sup1);
                if (lane == 0) {
                    dst1[rr * nw + 1] = bits2;
                    if (do1) dst1[rr * nw] = bits1;
                }
            }
        }
    }
    __syncthreads();

    // ======== serial NMS walk (thread 0, alive in regs), OVERLAPPED with
    //          output zero-fill by warps 1..7 ========
    if (tid == 0) {
        unsigned alive[16];
#pragma unroll
        for (int ww = 0; ww < 16; ++ww) {
            int n = K - ww * 32;
            alive[ww] = (n >= 32) ? 0xFFFFFFFFu : (n > 0 ? ((1u << n) - 1u) : 0u);
        }
        int cnt = 0;
#pragma unroll
        for (int W = 0; W < 16; ++W) {
            const int nw = 16 - W;
            const unsigned* blk = mat + tri_base(W);
            unsigned cur = alive[W];
            while (cur) {
                int bit = __ffs(cur) - 1;
                pord[cnt++] = (W << 5) + bit;
                const unsigned* mrow = blk + bit * nw;
                cur &= ~mrow[0];                 // self bit clears (iou=1 > TH)
                cur &= ~(1u << bit);
#pragma unroll
                for (int ww = W + 1; ww < 16; ++ww)
                    alive[ww] &= ~mrow[ww - W];
            }
        }
        misc[7] = (unsigned)cnt;
    } else if (tid >= 32) {
        for (int e = tid - 32; e < TOPK * 5; e += NT - 32) outp[e] = 0.0f;
    }
    __syncthreads();

    // ======== writeout (live rows only; rest already zero) ========
    const int cnt = (int)misc[7];
    for (int t = tid; t < cnt; t += NT) {
        int p = pord[t];
        float4 bb = bx4[p];
        outp[t * 5 + 0] = __uint_as_float((unsigned)(sel[p] >> 32));
        outp[t * 5 + 1] = bb.x;
        outp[t * 5 + 2] = bb.y;
        outp[t * 5 + 3] = bb.z;
        outp[t * 5 + 4] = bb.w;
    }
}

extern "C" void kernel_launch(void* const* d_in, const int* in_sizes, int n_in,
                              void* d_out, int out_size) {
    const float* arm_loc  = (const float*)d_in[0];
    const float* arm_conf = (const float*)d_in[1];
    const float* odm_loc  = (const float*)d_in[2];
    const float* odm_conf = (const float*)d_in[3];
    const float* priors   = (const float*)d_in[4];
    float* out = (float*)d_out;

    cudaFuncSetAttribute(task_kernel, cudaFuncAttributeMaxDynamicSharedMemorySize,
                         SMEM_TOTAL);

    int total = BATCH * PNUM;
    prep_kernel<<<(total + 255) / 256, 256>>>(arm_loc, arm_conf, odm_loc, odm_conf,
                                              priors);
    task_kernel<<<BATCH * NCLS, NT, SMEM_TOTAL>>>(out);
}

// round 17
// speedup vs baseline: 1.4804x; 1.0276x over previous
#include <cuda_runtime.h>

#define PNUM 16320
#define BATCH 32
#define NCLS 21
#define TOPK 500
#define CONF_THV 0.01f
#define NMS_THV 0.45f
#define OBJ_THV 0.01f
#define NT 256
// TH/(1+TH) for the transformed suppression test
#define NMS_COEF 0.310344827586206896f
#define NQ4 4080   // PNUM/4 float4 loads

// ---- device scratch (no allocations allowed) ----
__device__ float4 g_boxes[BATCH * PNUM];                 // decoded boxes (x1,y1,x2,y2)
__device__ float  g_scores[BATCH * (NCLS - 1) * PNUM];   // arm-masked scores, [B][20][P]

// ---- shared memory layout (bytes) ----
#define OFF_MISC   0        // 64 (16 u32)
#define OFF_SEL    64       // 512*8 = 4096 (u64 keys: score||~idx)
#define OFF_BOX    4160     // 512*16 = 8192 (16B aligned)
#define OFF_AREA   12352    // 2048  (holds c_i = NMS_COEF * area_i)
#define OFF_PORD   14400    // 2048
#define OFF_MAT    16448    // triangle-packed 4352 words = 17408
#define SMEM_TOTAL 33856    // 5 blocks/SM (reg-capped), single wave
// overlays inside MAT (dead until matrix phase)
#define OFF_HIST   16448    // 2048*4 = 8192
#define OFF_PART   24640    // 256*4
#define OFF_WSUM   25664    // 8*4
#define OFF_EQ     25696    // 512*8 = 4096 (u64 boundary-bin keys)

// misc: 1=ncomp 4=take 6=K 7=cnt 8=bsel 9=neq

// triangle packing: rows grouped by block rb=r>>5; row r stores words rb..15
__host__ __device__ __forceinline__ int tri_base(int rb) {
    return 512 * rb - 16 * rb * (rb - 1);
}

// 72 equal 32x32 tiles (p=column pair, rb=row block; rb <= 2p+1), 9 per warp
__device__ __constant__ unsigned char TP[72] = {
    0,0, 1,1,1,1, 2,2,2,2,2,2, 3,3,3,3,3,3,3,3,
    4,4,4,4,4,4,4,4,4,4, 5,5,5,5,5,5,5,5,5,5,5,5,
    6,6,6,6,6,6,6,6,6,6,6,6,6,6, 7,7,7,7,7,7,7,7,7,7,7,7,7,7,7,7};
__device__ __constant__ unsigned char TRB[72] = {
    0,1, 0,1,2,3, 0,1,2,3,4,5, 0,1,2,3,4,5,6,7,
    0,1,2,3,4,5,6,7,8,9, 0,1,2,3,4,5,6,7,8,9,10,11,
    0,1,2,3,4,5,6,7,8,9,10,11,12,13, 0,1,2,3,4,5,6,7,8,9,10,11,12,13,14,15};

// =====================================================================
// Kernel 1: cascaded decode + arm-masked score transpose
// =====================================================================
__global__ void prep_kernel(const float* __restrict__ arm_loc,
                            const float* __restrict__ arm_conf,
                            const float* __restrict__ odm_loc,
                            const float* __restrict__ odm_conf,
                            const float* __restrict__ priors) {
    int idx = blockIdx.x * blockDim.x + threadIdx.x;
    if (idx >= BATCH * PNUM) return;
    int b = idx / PNUM;
    int p = idx % PNUM;

    float pcx = priors[p * 4 + 0];
    float pcy = priors[p * 4 + 1];
    float pw  = priors[p * 4 + 2];
    float ph  = priors[p * 4 + 3];

    const float* al = arm_loc + (size_t)idx * 4;
    const float* ol = odm_loc + (size_t)idx * 4;

    float cx = pcx + al[0] * 0.1f * pw;
    float cy = pcy + al[1] * 0.1f * ph;
    float w  = pw * expf(al[2] * 0.2f);
    float h  = ph * expf(al[3] * 0.2f);
    float mnx = cx - w * 0.5f;
    float mny = cy - h * 0.5f;
    float mxx = mnx + w;
    float mxy = mny + h;
    float dcx = (mxx + mnx) * 0.5f;
    float dcy = (mxy + mny) * 0.5f;
    float dw  = mxx - mnx;
    float dh  = mxy - mny;

    float cx2 = dcx + ol[0] * 0.1f * dw;
    float cy2 = dcy + ol[1] * 0.1f * dh;
    float w2  = dw * expf(ol[2] * 0.2f);
    float h2  = dh * expf(ol[3] * 0.2f);
    float x1 = cx2 - w2 * 0.5f;
    float y1 = cy2 - h2 * 0.5f;
    float x2 = x1 + w2;
    float y2 = y1 + h2;
    g_boxes[idx] = make_float4(x1, y1, x2, y2);

    bool armpass = arm_conf[(size_t)idx * 2 + 1] > OBJ_THV;
    const float* oc = odm_conf + (size_t)idx * NCLS;
#pragma unroll
    for (int c = 1; c < NCLS; ++c) {
        float v = armpass ? oc[c] : 0.0f;
        g_scores[((size_t)(b * (NCLS - 1) + (c - 1))) * PNUM + p] = v;
    }
}

// =====================================================================
// Kernel 2: per (image,class), 256 threads. Linear-bin 2-scan exact
// top-K select (collective-free, unordered atomic compaction),
// hybrid shfl/smem u64 bitonic sort, adjacent-pair LUT-balanced
// suppression matrix, serial NMS walk overlapped with zero-fill.
// =====================================================================
__global__ void __launch_bounds__(NT, 5) task_kernel(float* __restrict__ out) {
    extern __shared__ __align__(16) char smraw[];
    unsigned*           misc = (unsigned*)(smraw + OFF_MISC);
    unsigned long long* sel  = (unsigned long long*)(smraw + OFF_SEL);
    float4*             bx4  = (float4*)(smraw + OFF_BOX);
    float*              s_c  = (float*)(smraw + OFF_AREA);
    int*                pord = (int*)(smraw + OFF_PORD);
    unsigned*           mat  = (unsigned*)(smraw + OFF_MAT);
    unsigned*           hist = (unsigned*)(smraw + OFF_HIST);
    unsigned*           part = (unsigned*)(smraw + OFF_PART);
    unsigned*           wsum = (unsigned*)(smraw + OFF_WSUM);
    unsigned long long* eqk  = (unsigned long long*)(smraw + OFF_EQ);

    const int tid = threadIdx.x;
    const int b   = blockIdx.x / NCLS;
    const int cl  = blockIdx.x % NCLS;
    float* outp = out + (size_t)(b * NCLS + cl) * (TOPK * 5);

    if (cl == 0) {  // background class: all zeros
        for (int e = tid; e < TOPK * 5; e += NT) outp[e] = 0.0f;
        return;
    }

    const float* __restrict__ sp =
        g_scores + (size_t)(b * (NCLS - 1) + (cl - 1)) * PNUM;
    const float4* __restrict__ sp4 = (const float4*)sp;

    // ======== SCAN 1: 2048 linear-bin histogram (bin = s*2047, monotone) ====
    for (int h = tid; h < 2048; h += NT) hist[h] = 0u;
    if (tid < 16) misc[tid] = 0u;
    __syncthreads();

    for (int j4 = tid; j4 < NQ4; j4 += NT) {   // collective-free
        float4 sv = sp4[j4];
#pragma unroll
        for (int e = 0; e < 4; ++e) {
            float s = (e == 0) ? sv.x : (e == 1) ? sv.y : (e == 2) ? sv.z : sv.w;
            if (s > CONF_THV)
                atomicAdd(&hist[min((int)(s * 2047.0f), 2047)], 1u);
        }
    }
    __syncthreads();
    {   // reduce 2048 bins: 8/thread -> part[256] -> wsum[8]
        unsigned v = 0;
#pragma unroll
        for (int q = 0; q < 8; ++q) v += hist[tid * 8 + q];
        part[tid] = v;
#pragma unroll
        for (int o = 16; o; o >>= 1) v += __shfl_down_sync(0xFFFFFFFFu, v, o);
        if ((tid & 31) == 0) wsum[tid >> 5] = v;
    }
    __syncthreads();
    if (tid == 0) {
        unsigned total = 0;
        for (int l = 0; l < 8; ++l) total += wsum[l];
        unsigned K = total < TOPK ? total : TOPK;
        misc[6] = K;
        if (K > 0) {
            unsigned rem = K, cum = 0;
            int l = 7;
            for (;; --l) { unsigned v = wsum[l]; if (cum + v >= rem) break; cum += v; }
            int p = l * 32 + 31;
            for (;; --p) { unsigned v = part[p]; if (cum + v >= rem) break; cum += v; }
            int bb = p * 8 + 7;
            for (;; --bb) { unsigned v = hist[bb]; if (cum + v >= rem) break; cum += v; }
            misc[8] = (unsigned)bb;
            misc[4] = rem - cum;       // take from boundary bin
        }
    }
    __syncthreads();

    const int K = (int)misc[6];
    if (K == 0) {
        for (int e = tid; e < TOPK * 5; e += NT) outp[e] = 0.0f;
        return;
    }

    // ======== SCAN 2: unordered compact (plain atomics; order fixed by sort) =
    const int bsel = (int)misc[8];
    for (int j4 = tid; j4 < NQ4; j4 += NT) {   // collective-free
        float4 sv = sp4[j4];
#pragma unroll
        for (int e = 0; e < 4; ++e) {
            float s = (e == 0) ? sv.x : (e == 1) ? sv.y : (e == 2) ? sv.z : sv.w;
            if (s > CONF_THV) {
                int bin = min((int)(s * 2047.0f), 2047);
                if (bin >= bsel) {      // ~3% of elements reach here
                    unsigned long long key =
                        ((unsigned long long)__float_as_uint(s) << 32) |
                        (unsigned long long)(0xFFFFFFFFu - (unsigned)(j4 * 4 + e));
                    if (bin > bsel) {
                        unsigned pos = atomicAdd(&misc[1], 1u);
                        sel[pos] = key;
                    } else {
                        unsigned p = atomicAdd(&misc[9], 1u);
                        if (p < 512) eqk[p] = key;
                    }
                }
            }
        }
    }
    __syncthreads();
    if (tid == 0) {    // pick the 'take' largest keys from the boundary bin
        int neq = (int)misc[9]; if (neq > 512) neq = 512;
        int tk = (int)misc[4]; if (tk > neq) tk = neq;
        int base = (int)misc[1];
        for (int t = 0; t < tk; ++t) {
            unsigned long long best = 0ull; int bi = 0;
            for (int q = 0; q < neq; ++q)
                if (eqk[q] > best) { best = eqk[q]; bi = q; }
            eqk[bi] = 0ull;
            sel[base + t] = best;
        }
        misc[1] = (unsigned)(base + tk);
    }
    __syncthreads();
    for (int i = tid; i < 512; i += NT)
        if (i >= K) sel[i] = (unsigned long long)(0xBFFFFFFFu - i);  // hi32=0: sorts last
    __syncthreads();

    // ======== hybrid bitonic sort: 512 u64 keys, descending ========
    {
        unsigned long long e0 = sel[tid], e1 = sel[tid + 256];
#pragma unroll
        for (unsigned k = 2; k <= 32; k <<= 1) {
#pragma unroll
            for (unsigned jj = k >> 1; jj > 0; jj >>= 1) {
                unsigned long long p0 = __shfl_xor_sync(0xFFFFFFFFu, e0, jj);
                unsigned long long p1 = __shfl_xor_sync(0xFFFFFFFFu, e1, jj);
                bool lo = (((unsigned)tid & jj) == 0);
                bool up0 = ((((unsigned)tid) & k) == 0) == lo;
                bool up1 = ((((unsigned)tid + 256u) & k) == 0) == lo;
                e0 = up0 ? (e0 > p0 ? e0 : p0) : (e0 < p0 ? e0 : p0);
                e1 = up1 ? (e1 > p1 ? e1 : p1) : (e1 < p1 ? e1 : p1);
            }
        }
        sel[tid] = e0; sel[tid + 256] = e1;
        __syncthreads();
#pragma unroll 1
        for (unsigned k = 64; k <= 512; k <<= 1) {
            for (unsigned jj = k >> 1; jj >= 32; jj >>= 1) {
#pragma unroll
                for (int half = 0; half < 512; half += NT) {
                    unsigned i = (unsigned)(half + tid);
                    unsigned ixj = i ^ jj;
                    if (ixj > i) {
                        unsigned long long a = sel[i], x = sel[ixj];
                        bool g = x > a;
                        bool asc = ((i & k) == 0);
                        if (asc ? g : !g) { sel[i] = x; sel[ixj] = a; }
                    }
                }
                __syncthreads();
            }
            e0 = sel[tid]; e1 = sel[tid + 256];
#pragma unroll
            for (unsigned jj = 16; jj > 0; jj >>= 1) {
                unsigned long long p0 = __shfl_xor_sync(0xFFFFFFFFu, e0, jj);
                unsigned long long p1 = __shfl_xor_sync(0xFFFFFFFFu, e1, jj);
                bool lo = (((unsigned)tid & jj) == 0);
                bool up0 = ((((unsigned)tid) & k) == 0) == lo;
                bool up1 = ((((unsigned)tid + 256u) & k) == 0) == lo;
                e0 = up0 ? (e0 > p0 ? e0 : p0) : (e0 < p0 ? e0 : p0);
                e1 = up1 ? (e1 > p1 ? e1 : p1) : (e1 < p1 ? e1 : p1);
            }
            sel[tid] = e0; sel[tid + 256] = e1;
            __syncthreads();
        }
    }

    // ======== gather boxes + precompute c_i = NMS_COEF * area_i ========
    for (int i = tid; i < 512; i += NT) {
        float4 bb = make_float4(0.f, 0.f, 0.f, 0.f);
        float a = 0.f;
        if (i < K) {
            unsigned idx = 0xFFFFFFFFu - (unsigned)sel[i];
            bb = g_boxes[(size_t)b * PNUM + idx];
            a = (bb.z - bb.x) * (bb.w - bb.y);
        }
        bx4[i] = bb;
        s_c[i] = NMS_COEF * a;
    }
    __syncthreads();

    // ======== suppression matrix over 72 balanced adjacent-pair tiles ========
    // sup(i,j) == fmaf(iw, ih, -(c_i+c_j)) > 0 ; iw clamped, ih clamp dropped
    {
        const int w    = tid >> 5;
        const int lane = tid & 31;
#pragma unroll 1
        for (int tt = 0; tt < 9; ++tt) {
            const int t  = w + tt * 8;
            const int p  = TP[t];
            const int rb = TRB[t];
            const int W1 = 2 * p;
            const int W2 = W1 + 1;
            const int j1 = (W1 << 5) + lane;
            const int j2 = (W2 << 5) + lane;
            const float4 b1 = bx4[j1];
            const float  c1 = s_c[j1];
            const float4 b2 = bx4[j2];
            const float  c2 = s_c[j2];
            const bool do1 = (rb <= W1);               // warp-uniform
            const int nw = 16 - rb;
            unsigned* dst1 = mat + tri_base(rb) + (W1 - rb);
#pragma unroll 4
            for (int rr = 0; rr < 32; ++rr) {
                const int r = (rb << 5) + rr;
                const float4 bi = bx4[r];               // broadcast LDS.128
                const float  ci = s_c[r];
                float xx1 = fmaxf(bi.x, b2.x);
                float yy1 = fmaxf(bi.y, b2.y);
                float xx2 = fminf(bi.z, b2.z);
                float yy2 = fminf(bi.w, b2.w);
                float iw = fmaxf(xx2 - xx1, 0.0f);
                float ih = yy2 - yy1;                   // unclamped: safe
                bool sup2 = fmaf(iw, ih, -(ci + c2)) > 0.0f;
                unsigned bits2 = __ballot_sync(0xFFFFFFFFu, sup2);
                float ax1 = fmaxf(bi.x, b1.x);
                float ay1 = fmaxf(bi.y, b1.y);
                float ax2 = fminf(bi.z, b1.z);
                float ay2 = fminf(bi.w, b1.w);
                float aw = fmaxf(ax2 - ax1, 0.0f);
                float ah = ay2 - ay1;                   // unclamped: safe
                bool sup1 = fmaf(aw, ah, -(ci + c1)) > 0.0f;
                unsigned bits1 = __ballot_sync(0xFFFFFFFFu, sup1);
                if (lane == 0) {
                    dst1[rr * nw + 1] = bits2;
                    if (do1) dst1[rr * nw] = bits1;
                }
            }
        }
    }
    __syncthreads();

    // ======== serial NMS walk (thread 0, alive in regs), OVERLAPPED with
    //          output zero-fill by warps 1..7 ========
    if (tid == 0) {
        unsigned alive[16];
#pragma unroll
        for (int ww = 0; ww < 16; ++ww) {
            int n = K - ww * 32;
            alive[ww] = (n >= 32) ? 0xFFFFFFFFu : (n > 0 ? ((1u << n) - 1u) : 0u);
        }
        int cnt = 0;
#pragma unroll
        for (int W = 0; W < 16; ++W) {
            const int nw = 16 - W;
            const unsigned* blk = mat + tri_base(W);
            unsigned cur = alive[W];
            while (cur) {
                int bit = __ffs(cur) - 1;
                pord[cnt++] = (W << 5) + bit;
                const unsigned* mrow = blk + bit * nw;
                cur &= ~mrow[0];                 // self bit clears (iou=1 > TH)
                cur &= ~(1u << bit);
#pragma unroll
                for (int ww = W + 1; ww < 16; ++ww)
                    alive[ww] &= ~mrow[ww - W];
            }
        }
        misc[7] = (unsigned)cnt;
    } else if (tid >= 32) {
        for (int e = tid - 32; e < TOPK * 5; e += NT - 32) outp[e] = 0.0f;
    }
    __syncthreads();

    // ======== writeout (live rows only; rest already zero) ========
    const int cnt = (int)misc[7];
    for (int t = tid; t < cnt; t += NT) {
        int p = pord[t];
        float4 bb = bx4[p];
        outp[t * 5 + 0] = __uint_as_float((unsigned)(sel[p] >> 32));
        outp[t * 5 + 1] = bb.x;
        outp[t * 5 + 2] = bb.y;
        outp[t * 5 + 3] = bb.z;
        outp[t * 5 + 4] = bb.w;
    }
}

extern "C" void kernel_launch(void* const* d_in, const int* in_sizes, int n_in,
                              void* d_out, int out_size) {
    const float* arm_loc  = (const float*)d_in[0];
    const float* arm_conf = (const float*)d_in[1];
    const float* odm_loc  = (const float*)d_in[2];
    const float* odm_conf = (const float*)d_in[3];
    const float* priors   = (const float*)d_in[4];
    float* out = (float*)d_out;

    cudaFuncSetAttribute(task_kernel, cudaFuncAttributeMaxDynamicSharedMemorySize,
                         SMEM_TOTAL);

    int total = BATCH * PNUM;
    prep_kernel<<<(total + 255) / 256, 256>>>(arm_loc, arm_conf, odm_loc, odm_conf,
                                              priors);
    task_kernel<<<BATCH * NCLS, NT, SMEM_TOTAL>>>(out);
}